// round 1
// baseline (speedup 1.0000x reference)
#include <cuda_runtime.h>
#include <cuda_bf16.h>
#include <math.h>

#define BB 256
#define HH 512
#define EE 512
#define VV 10000
#define TT 48
#define TTOT 9436

// ---------------- scratch (device globals; no allocation allowed) -------------
__device__ float g_Xc[BB * 2048];          // conv output flattened [B,2048]
__device__ float g_F0[BB * HH];            // pre-BN fc output
__device__ float g_F[BB * HH];             // BN'd features
__device__ float g_Emb[TTOT * EE];         // packed caption embeddings
__device__ float g_Xpad[TT * BB * EE];     // padded [T,B,E]
__device__ float g_xA[TT * BB * HH];       // x_t @ attn_w_x^T + attn_b
__device__ float g_xC[TT * BB * HH];       // x_t @ comb_w_x^T + comb_b
__device__ float g_hx[BB * HH];
__device__ float g_Gh[BB * 3 * HH];
__device__ float g_Gi[BB * 3 * HH];
__device__ float g_L[BB * HH];             // attn logits
__device__ float g_applied[BB * HH];
__device__ float g_inp[BB * HH];
__device__ float g_Cat[BB * 2 * HH];
__device__ float g_Y[BB * 2 * HH];

// ---------------- generic SGEMM: C[M,N] = A[M,K] @ W[N,K]^T (+bias)(+add)(relu)
// BM=BN=64, BK=16, 256 threads, 4x4 per-thread microtile.
__global__ __launch_bounds__(256) void sgemm_kernel(
    const float* __restrict__ A, int lda,
    const float* __restrict__ W, int ldw,
    const float* __restrict__ bias,
    const float* __restrict__ add,
    float* __restrict__ C, int ldc,
    int M, int N, int K, int act)
{
    __shared__ float As[16][64];
    __shared__ float Ws[16][64];
    const int m0 = blockIdx.y * 64;
    const int n0 = blockIdx.x * 64;
    const int tid = threadIdx.x;
    const int tm = tid >> 4;    // 0..15
    const int tn = tid & 15;    // 0..15
    const int lr  = tid >> 2;        // 0..63
    const int lk4 = (tid & 3) * 4;   // 0,4,8,12

    float acc[4][4];
#pragma unroll
    for (int i = 0; i < 4; i++)
#pragma unroll
        for (int j = 0; j < 4; j++) acc[i][j] = 0.f;

    for (int kk = 0; kk < K; kk += 16) {
        // A tile (64 rows x 16 k), stored transposed
        {
            int row = m0 + lr;
            float4 v = make_float4(0.f, 0.f, 0.f, 0.f);
            if (row < M)
                v = *reinterpret_cast<const float4*>(A + (size_t)row * lda + kk + lk4);
            As[lk4 + 0][lr] = v.x; As[lk4 + 1][lr] = v.y;
            As[lk4 + 2][lr] = v.z; As[lk4 + 3][lr] = v.w;
        }
        // W tile (64 cols x 16 k)
        {
            int col = n0 + lr;
            float4 v = make_float4(0.f, 0.f, 0.f, 0.f);
            if (col < N)
                v = *reinterpret_cast<const float4*>(W + (size_t)col * ldw + kk + lk4);
            Ws[lk4 + 0][lr] = v.x; Ws[lk4 + 1][lr] = v.y;
            Ws[lk4 + 2][lr] = v.z; Ws[lk4 + 3][lr] = v.w;
        }
        __syncthreads();
#pragma unroll
        for (int k = 0; k < 16; k++) {
            float4 a4 = *reinterpret_cast<const float4*>(&As[k][tm * 4]);
            float4 b4 = *reinterpret_cast<const float4*>(&Ws[k][tn * 4]);
            float a[4] = {a4.x, a4.y, a4.z, a4.w};
            float b[4] = {b4.x, b4.y, b4.z, b4.w};
#pragma unroll
            for (int i = 0; i < 4; i++)
#pragma unroll
                for (int j = 0; j < 4; j++) acc[i][j] += a[i] * b[j];
        }
        __syncthreads();
    }

#pragma unroll
    for (int i = 0; i < 4; i++) {
        int row = m0 + tm * 4 + i;
        if (row >= M) continue;
#pragma unroll
        for (int j = 0; j < 4; j++) {
            int col = n0 + tn * 4 + j;
            if (col >= N) continue;
            float v = acc[i][j];
            if (bias) v += bias[col];
            if (add)  v += add[(size_t)row * ldc + col];
            if (act)  v = fmaxf(v, 0.f);
            C[(size_t)row * ldc + col] = v;
        }
    }
}

// ---------------- direct conv: features[B,2048,8,8] * conv_w[32,2048,3,3], pad1
// one block per image; 4 cin-quarters x (4 cout-groups x 16 spatial-quads)
__global__ __launch_bounds__(256) void conv_kernel(
    const float* __restrict__ features,
    const float* __restrict__ conv_w,
    const float* __restrict__ conv_b)
{
    __shared__ float sF[4][4][100];       // padded 10x10 per (quarter, cin)
    __shared__ float sW[4][4][32][9];
    __shared__ float sRed[2][64][32];

    const int b = blockIdx.x;
    const int tid = threadIdx.x;
    const int qid = tid >> 6;       // cin quarter 0..3
    const int t2  = tid & 63;
    const int coutg = t2 >> 4;      // 0..3 (8 couts each)
    const int sg    = t2 & 15;      // 0..15 (4 spatial each)

    // zero padded feature smem once (borders stay zero)
    for (int e = tid; e < 4 * 4 * 100; e += 256)
        (&sF[0][0][0])[e] = 0.f;

    int fb[4];
#pragma unroll
    for (int sp = 0; sp < 4; sp++) {
        int s = sg * 4 + sp;
        fb[sp] = (s >> 3) * 10 + (s & 7);   // (y)*10 + x in padded grid
    }

    float acc[8][4];
#pragma unroll
    for (int co = 0; co < 8; co++)
#pragma unroll
        for (int sp = 0; sp < 4; sp++) acc[co][sp] = 0.f;

    for (int cbase = 0; cbase < 512; cbase += 4) {
        __syncthreads();
        // load features interior: 4 quarters x 4 cin x 64 spatial
        for (int e = tid; e < 1024; e += 256) {
            int q = e >> 8, c = (e >> 6) & 3, s = e & 63;
            int y = s >> 3, x = s & 7;
            int cin = q * 512 + cbase + c;
            sF[q][c][(y + 1) * 10 + (x + 1)] =
                features[((size_t)b * 2048 + cin) * 64 + s];
        }
        // load weights: 4 x 4 x 32 x 9
        for (int e = tid; e < 4608; e += 256) {
            int q = e / 1152, r = e % 1152;
            int c = r / 288, r2 = r % 288;
            int cout = r2 / 9, k = r2 % 9;
            int cin = q * 512 + cbase + c;
            sW[q][c][cout][k] = conv_w[((size_t)cout * 2048 + cin) * 9 + k];
        }
        __syncthreads();

#pragma unroll
        for (int c = 0; c < 4; c++) {
            const float* fp = &sF[qid][c][0];
            const float* wp = &sW[qid][c][0][0];
#pragma unroll
            for (int ky = 0; ky < 3; ky++) {
#pragma unroll
                for (int kx = 0; kx < 3; kx++) {
                    float wv[8];
#pragma unroll
                    for (int co = 0; co < 8; co++)
                        wv[co] = wp[(coutg * 8 + co) * 9 + ky * 3 + kx];
#pragma unroll
                    for (int sp = 0; sp < 4; sp++) {
                        float fv = fp[fb[sp] + ky * 10 + kx];
#pragma unroll
                        for (int co = 0; co < 8; co++)
                            acc[co][sp] += fv * wv[co];
                    }
                }
            }
        }
    }

    // reduce across the 4 cin quarters
    __syncthreads();
    if (qid >= 2) {
#pragma unroll
        for (int co = 0; co < 8; co++)
#pragma unroll
            for (int sp = 0; sp < 4; sp++)
                sRed[qid - 2][t2][co * 4 + sp] = acc[co][sp];
    }
    __syncthreads();
    if (qid < 2) {
#pragma unroll
        for (int co = 0; co < 8; co++)
#pragma unroll
            for (int sp = 0; sp < 4; sp++)
                acc[co][sp] += sRed[qid][t2][co * 4 + sp];
    }
    __syncthreads();
    if (qid == 1) {
#pragma unroll
        for (int co = 0; co < 8; co++)
#pragma unroll
            for (int sp = 0; sp < 4; sp++)
                sRed[0][t2][co * 4 + sp] = acc[co][sp];
    }
    __syncthreads();
    if (qid == 0) {
#pragma unroll
        for (int co = 0; co < 8; co++) {
            int cout = coutg * 8 + co;
            float bval = conv_b[cout];
#pragma unroll
            for (int sp = 0; sp < 4; sp++) {
                int s = sg * 4 + sp;
                g_Xc[(size_t)b * 2048 + cout * 64 + s] =
                    acc[co][sp] + sRed[0][t2][co * 4 + sp] + bval;
            }
        }
    }
}

// ---------------- BatchNorm1d with batch stats (training mode)
__global__ void bn_kernel(const float* __restrict__ bn_g,
                          const float* __restrict__ bn_b)
{
    __shared__ float red[256];
    const int h = blockIdx.x;     // 0..511
    const int b = threadIdx.x;    // 0..255
    float v = g_F0[(size_t)b * HH + h];
    red[b] = v;
    __syncthreads();
    for (int s = 128; s > 0; s >>= 1) {
        if (b < s) red[b] += red[b + s];
        __syncthreads();
    }
    float mu = red[0] / 256.f;
    __syncthreads();
    float d = v - mu;
    red[b] = d * d;
    __syncthreads();
    for (int s = 128; s > 0; s >>= 1) {
        if (b < s) red[b] += red[b + s];
        __syncthreads();
    }
    float var = red[0] / 256.f;
    float scale = rsqrtf(var + 1e-5f);
    g_F[(size_t)b * HH + h] = d * scale * bn_g[h] + bn_b[h];
}

// ---------------- gather packed embeddings into padded [T,B,E]
__global__ void gather_kernel(const int* __restrict__ pack_idx)
{
    int tb = blockIdx.x;           // t*256 + b
    int t = tb >> 8, b = tb & 255;
    int e = threadIdx.x;           // 0..511
    int idx = pack_idx[b * TT + t];
    float v = (idx >= 0) ? g_Emb[(size_t)idx * EE + e] : 0.f;
    g_Xpad[(size_t)tb * EE + e] = v;
}

__global__ void init_hx_kernel(const float* __restrict__ states)
{
    int i = blockIdx.x * blockDim.x + threadIdx.x;
    g_hx[i] = states[i];
}

// ---------------- softmax over h + elementwise attention gating
__global__ void softmax_applied_kernel()
{
    __shared__ float red[512];
    const int b = blockIdx.x;
    const int h = threadIdx.x;
    float v = g_L[(size_t)b * HH + h];
    red[h] = v;
    __syncthreads();
    for (int s = 256; s > 0; s >>= 1) {
        if (h < s) red[h] = fmaxf(red[h], red[h + s]);
        __syncthreads();
    }
    float mx = red[0];
    __syncthreads();
    float e = expf(v - mx);
    red[h] = e;
    __syncthreads();
    for (int s = 256; s > 0; s >>= 1) {
        if (h < s) red[h] += red[h + s];
        __syncthreads();
    }
    float aw = e / red[0];
    g_applied[(size_t)b * HH + h] = g_F[(size_t)b * HH + h] * aw;
}

// ---------------- GRU gate combine + hidden update + capture at t==len-1
__global__ void gru_gate_kernel(const int* __restrict__ lengths,
                                float* __restrict__ hiddens, int t)
{
    const int b = blockIdx.x;
    const int h = threadIdx.x;
    size_t o = (size_t)b * 1536;
    float ir = g_Gi[o + h],         hr = g_Gh[o + h];
    float iz = g_Gi[o + 512 + h],   hz = g_Gh[o + 512 + h];
    float in_ = g_Gi[o + 1024 + h], hn = g_Gh[o + 1024 + h];
    float r = 1.f / (1.f + expf(-(ir + hr)));
    float z = 1.f / (1.f + expf(-(iz + hz)));
    float n = tanhf(in_ + r * hn);
    float hprev = g_hx[(size_t)b * HH + h];
    float hnew = (1.f - z) * n + z * hprev;
    g_hx[(size_t)b * HH + h] = hnew;
    if (t == lengths[b] - 1)
        hiddens[(size_t)b * HH + h] = hnew;
}

// ---------------- build concat [hiddens, F]
__global__ void cat_kernel(const float* __restrict__ hiddens)
{
    const int b = blockIdx.x;
    const int i = threadIdx.x;   // 0..1023
    float v = (i < 512) ? hiddens[(size_t)b * HH + i]
                        : g_F[(size_t)b * HH + (i - 512)];
    g_Cat[(size_t)b * 1024 + i] = v;
}

// ---------------- final linear(1024->1) + sigmoid
__global__ void head_kernel(const float* __restrict__ lin3_w,
                            const float* __restrict__ lin3_b,
                            float* __restrict__ out)
{
    __shared__ float red[256];
    const int b = blockIdx.x;
    const int tid = threadIdx.x;
    float acc = 0.f;
#pragma unroll
    for (int k = 0; k < 4; k++) {
        int idx = tid + k * 256;
        acc += g_Y[(size_t)b * 1024 + idx] * lin3_w[idx];
    }
    red[tid] = acc;
    __syncthreads();
    for (int s = 128; s > 0; s >>= 1) {
        if (tid < s) red[tid] += red[tid + s];
        __syncthreads();
    }
    if (tid == 0) {
        float x = red[0] + lin3_b[0];
        out[b] = 1.f / (1.f + expf(-x));
    }
}

// ---------------- host orchestration ------------------------------------------
static void sgemm(const float* A, int lda, const float* W, int ldw,
                  const float* bias, const float* add,
                  float* C, int ldc, int M, int N, int K, int act)
{
    dim3 grid(N / 64, (M + 63) / 64);
    sgemm_kernel<<<grid, 256>>>(A, lda, W, ldw, bias, add, C, ldc, M, N, K, act);
}

extern "C" void kernel_launch(void* const* d_in, const int* in_sizes, int n_in,
                              void* d_out, int out_size)
{
    const float* features = (const float*)d_in[0];
    const float* captions = (const float*)d_in[1];
    const float* states   = (const float*)d_in[2];
    const int*   pack_idx = (const int*)d_in[3];
    const int*   lengths  = (const int*)d_in[4];
    const float* conv_w   = (const float*)d_in[5];
    const float* conv_b   = (const float*)d_in[6];
    const float* fc_w     = (const float*)d_in[7];
    const float* fc_b     = (const float*)d_in[8];
    const float* bn_g     = (const float*)d_in[9];
    const float* bn_b     = (const float*)d_in[10];
    const float* fc2_w    = (const float*)d_in[11];
    const float* fc2_b    = (const float*)d_in[12];
    const float* attn_w   = (const float*)d_in[13];
    const float* attn_b   = (const float*)d_in[14];
    const float* comb_w   = (const float*)d_in[15];
    const float* comb_b   = (const float*)d_in[16];
    const float* gru_wih  = (const float*)d_in[17];
    const float* gru_whh  = (const float*)d_in[18];
    const float* gru_bih  = (const float*)d_in[19];
    const float* gru_bhh  = (const float*)d_in[20];
    const float* lin_w    = (const float*)d_in[21];
    const float* lin_b    = (const float*)d_in[22];
    const float* lin3_w   = (const float*)d_in[23];
    const float* lin3_b   = (const float*)d_in[24];

    float* out = (float*)d_out;            // [0:256) sigmoid, [256: ) hiddens
    float* hiddens = out + 256;

    // scratch pointers (device globals)
    float *pXc, *pF0, *pEmb, *pXpad, *pxA, *pxC, *phx, *pGh, *pGi;
    float *pL, *pApplied, *pInp, *pCat, *pY;
    cudaGetSymbolAddress((void**)&pXc, g_Xc);
    cudaGetSymbolAddress((void**)&pF0, g_F0);
    cudaGetSymbolAddress((void**)&pEmb, g_Emb);
    cudaGetSymbolAddress((void**)&pXpad, g_Xpad);
    cudaGetSymbolAddress((void**)&pxA, g_xA);
    cudaGetSymbolAddress((void**)&pxC, g_xC);
    cudaGetSymbolAddress((void**)&phx, g_hx);
    cudaGetSymbolAddress((void**)&pGh, g_Gh);
    cudaGetSymbolAddress((void**)&pGi, g_Gi);
    cudaGetSymbolAddress((void**)&pL, g_L);
    cudaGetSymbolAddress((void**)&pApplied, g_applied);
    cudaGetSymbolAddress((void**)&pInp, g_inp);
    cudaGetSymbolAddress((void**)&pCat, g_Cat);
    cudaGetSymbolAddress((void**)&pY, g_Y);

    // 1) conv -> g_Xc
    conv_kernel<<<256, 256>>>(features, conv_w, conv_b);
    // 2) fc: F0 = Xc @ fc_w^T + fc_b
    sgemm(pXc, 2048, fc_w, 2048, fc_b, nullptr, pF0, HH, BB, HH, 2048, 0);
    // 3) BN -> g_F
    bn_kernel<<<HH, 256>>>(bn_g, bn_b);
    // 4) emb = captions @ fc2_w^T + fc2_b
    sgemm(captions, VV, fc2_w, VV, fc2_b, nullptr, pEmb, EE, TTOT, EE, VV, 0);
    // 5) gather to padded [T,B,E]
    gather_kernel<<<TT * BB, EE>>>(pack_idx);
    // 6) x-part precompute GEMMs
    sgemm(pXpad, EE, attn_w, 1024, attn_b, nullptr, pxA, HH, TT * BB, HH, EE, 0);
    sgemm(pXpad, EE, comb_w, 1024, comb_b, nullptr, pxC, HH, TT * BB, HH, EE, 0);
    // 7) init hidden state
    init_hx_kernel<<<BB, HH>>>(states);

    // 8) sequential scan
    for (int t = 0; t < TT; t++) {
        // gh = hx @ gru_whh^T + gru_bhh
        sgemm(phx, HH, gru_whh, HH, gru_bhh, nullptr, pGh, 1536, BB, 1536, HH, 0);
        // attn logits: L = xA[t] + hx @ attn_w[:,512:]^T
        sgemm(phx, HH, attn_w + 512, 1024, nullptr,
              pxA + (size_t)t * BB * HH, pL, HH, BB, HH, HH, 0);
        softmax_applied_kernel<<<BB, HH>>>();
        // inp = relu(xC[t] + applied @ comb_w[:,512:]^T)
        sgemm(pApplied, HH, comb_w + 512, 1024, nullptr,
              pxC + (size_t)t * BB * HH, pInp, HH, BB, HH, HH, 1);
        // gi = inp @ gru_wih^T + gru_bih
        sgemm(pInp, HH, gru_wih, HH, gru_bih, nullptr, pGi, 1536, BB, 1536, HH, 0);
        gru_gate_kernel<<<BB, HH>>>(lengths, hiddens, t);
    }

    // 9) head
    cat_kernel<<<BB, 1024>>>(hiddens);
    sgemm(pCat, 1024, lin_w, 1024, lin_b, nullptr, pY, 1024, BB, 1024, 1024, 1);
    head_kernel<<<BB, 256>>>(lin3_w, lin3_b, out);
}

// round 2
// speedup vs baseline: 1.8817x; 1.8817x over previous
#include <cuda_runtime.h>
#include <cuda_bf16.h>
#include <math.h>

#define BB 256
#define HH 512
#define EE 512
#define VV 10000
#define TT 48
#define TTOT 9436

// ---------------- scratch (device globals; no allocation allowed) -------------
__device__ float g_Xc[BB * 2048];          // conv output flattened [B,2048]
__device__ float g_F0[BB * HH];            // pre-BN fc output
__device__ float g_F[BB * HH];             // BN'd features
__device__ float g_Emb[TTOT * EE];         // packed caption embeddings
__device__ float g_Xpad[TT * BB * EE];     // padded [T,B,E]
__device__ float g_xA[TT * BB * HH];       // x_t @ attn_w_x^T + attn_b
__device__ float g_xC[TT * BB * HH];       // x_t @ comb_w_x^T + comb_b
__device__ float g_hx[BB * HH];
__device__ float g_GhL[BB * 2048];         // [Gh(1536) | attn logits h-part(512)]
__device__ float g_Gi[BB * 3 * HH];
__device__ float g_applied[BB * HH];
__device__ float g_inp[BB * HH];
__device__ float g_Cat[BB * 2 * HH];
__device__ float g_Y[BB * 2 * HH];
__device__ float g_Wpack[2048 * 512];      // rows 0..1535: gru_whh; 1536..2047: attn_w[:,512:]

// ---------------- tf32 helpers ------------------------------------------------
__device__ __forceinline__ unsigned f2tf32(float x) {
    unsigned r;
    asm("cvt.rna.tf32.f32 %0, %1;" : "=r"(r) : "f"(x));
    return r;
}

__device__ __forceinline__ void mma_tf32(float c[4],
    unsigned a0, unsigned a1, unsigned a2, unsigned a3,
    unsigned b0, unsigned b1)
{
    asm volatile(
        "mma.sync.aligned.m16n8k8.row.col.f32.tf32.tf32.f32 "
        "{%0,%1,%2,%3}, {%4,%5,%6,%7}, {%8,%9}, {%0,%1,%2,%3};"
        : "+f"(c[0]), "+f"(c[1]), "+f"(c[2]), "+f"(c[3])
        : "r"(a0), "r"(a1), "r"(a2), "r"(a3), "r"(b0), "r"(b1));
}

// ---------------- TF32x3 GEMM: C[M,N] = A[M,K] @ W[N,K]^T (+bias)(+add)(relu)
// BM=BN=64, BK=16, 128 threads (4 warps, 2x2), warp tile 32x32.
// Requires: N % 64 == 0, K % 16 == 0, lda/ldw % 4 == 0. M guarded.
__global__ __launch_bounds__(128) void tgemm_kernel(
    const float* __restrict__ A, int lda,
    const float* __restrict__ W, int ldw,
    const float* __restrict__ bias,
    const float* __restrict__ add,
    float* __restrict__ C, int ldc,
    int M, int N, int K, int act)
{
    __shared__ float Ah[64 * 20], Al[64 * 20];
    __shared__ float Wh[64 * 20], Wl[64 * 20];

    const int tid  = threadIdx.x;
    const int lane = tid & 31;
    const int warp = tid >> 5;
    const int wm = (warp & 1) * 32;
    const int wn = (warp >> 1) * 32;
    const int m0 = blockIdx.y * 64;
    const int n0 = blockIdx.x * 64;

    const int lr = tid >> 2;          // 0..31 -> rows lr, lr+32
    const int lc = (tid & 3) * 4;     // k offset 0,4,8,12

    float acc[2][4][4];
#pragma unroll
    for (int mt = 0; mt < 2; mt++)
#pragma unroll
        for (int nt = 0; nt < 4; nt++)
#pragma unroll
            for (int i = 0; i < 4; i++) acc[mt][nt][i] = 0.f;

    const int ar0 = m0 + lr, ar1 = m0 + lr + 32;
    const int wr0 = n0 + lr, wr1 = n0 + lr + 32;

    float4 av0, av1, wv0, wv1;
    const float4 z4 = make_float4(0.f, 0.f, 0.f, 0.f);

    // prologue load
    av0 = (ar0 < M) ? *(const float4*)(A + (size_t)ar0 * lda + lc) : z4;
    av1 = (ar1 < M) ? *(const float4*)(A + (size_t)ar1 * lda + lc) : z4;
    wv0 = *(const float4*)(W + (size_t)wr0 * ldw + lc);
    wv1 = *(const float4*)(W + (size_t)wr1 * ldw + lc);

    const unsigned* uAh = (const unsigned*)Ah;
    const unsigned* uAl = (const unsigned*)Al;
    const unsigned* uWh = (const unsigned*)Wh;
    const unsigned* uWl = (const unsigned*)Wl;
    const int krow = lane >> 2;   // 0..7
    const int kcol = lane & 3;    // 0..3

    for (int kk = 0; kk < K; kk += 16) {
        // split-store prefetched tile
        {
            float xs[4][4] = {{av0.x, av0.y, av0.z, av0.w},
                              {av1.x, av1.y, av1.z, av1.w},
                              {wv0.x, wv0.y, wv0.z, wv0.w},
                              {wv1.x, wv1.y, wv1.z, wv1.w}};
            float* Hd[4] = {Ah, Ah, Wh, Wh};
            float* Ld[4] = {Al, Al, Wl, Wl};
            int    rw[4] = {lr, lr + 32, lr, lr + 32};
#pragma unroll
            for (int q = 0; q < 4; q++) {
                float h[4], l[4];
#pragma unroll
                for (int i = 0; i < 4; i++) {
                    unsigned hb = f2tf32(xs[q][i]);
                    h[i] = __uint_as_float(hb);
                    l[i] = __uint_as_float(f2tf32(xs[q][i] - h[i]));
                }
                *(float4*)&Hd[q][rw[q] * 20 + lc] = make_float4(h[0], h[1], h[2], h[3]);
                *(float4*)&Ld[q][rw[q] * 20 + lc] = make_float4(l[0], l[1], l[2], l[3]);
            }
        }
        __syncthreads();

        // prefetch next tile
        if (kk + 16 < K) {
            int k2 = kk + 16 + lc;
            av0 = (ar0 < M) ? *(const float4*)(A + (size_t)ar0 * lda + k2) : z4;
            av1 = (ar1 < M) ? *(const float4*)(A + (size_t)ar1 * lda + k2) : z4;
            wv0 = *(const float4*)(W + (size_t)wr0 * ldw + k2);
            wv1 = *(const float4*)(W + (size_t)wr1 * ldw + k2);
        }

        // compute: 2 k-steps of 8
#pragma unroll
        for (int ks = 0; ks < 16; ks += 8) {
            unsigned ah[2][4], al_[2][4], bh[4][2], bl[4][2];
#pragma unroll
            for (int mt = 0; mt < 2; mt++) {
                int r = wm + mt * 16 + krow;
                int o0 = r * 20 + ks + kcol;
                int o1 = (r + 8) * 20 + ks + kcol;
                ah[mt][0] = uAh[o0];     ah[mt][1] = uAh[o1];
                ah[mt][2] = uAh[o0 + 4]; ah[mt][3] = uAh[o1 + 4];
                al_[mt][0] = uAl[o0];     al_[mt][1] = uAl[o1];
                al_[mt][2] = uAl[o0 + 4]; al_[mt][3] = uAl[o1 + 4];
            }
#pragma unroll
            for (int nt = 0; nt < 4; nt++) {
                int cn = wn + nt * 8 + krow;
                int o = cn * 20 + ks + kcol;
                bh[nt][0] = uWh[o]; bh[nt][1] = uWh[o + 4];
                bl[nt][0] = uWl[o]; bl[nt][1] = uWl[o + 4];
            }
#pragma unroll
            for (int mt = 0; mt < 2; mt++)
#pragma unroll
                for (int nt = 0; nt < 4; nt++) {
                    mma_tf32(acc[mt][nt], ah[mt][0], ah[mt][1], ah[mt][2], ah[mt][3],
                             bh[nt][0], bh[nt][1]);
                    mma_tf32(acc[mt][nt], ah[mt][0], ah[mt][1], ah[mt][2], ah[mt][3],
                             bl[nt][0], bl[nt][1]);
                    mma_tf32(acc[mt][nt], al_[mt][0], al_[mt][1], al_[mt][2], al_[mt][3],
                             bh[nt][0], bh[nt][1]);
                }
        }
        __syncthreads();
    }

    // epilogue
#pragma unroll
    for (int mt = 0; mt < 2; mt++) {
#pragma unroll
        for (int nt = 0; nt < 4; nt++) {
            int r0 = m0 + wm + mt * 16 + (lane >> 2);
            int c0 = n0 + wn + nt * 8 + (lane & 3) * 2;
#pragma unroll
            for (int i = 0; i < 4; i++) {
                int row = r0 + (i >> 1) * 8;
                int col = c0 + (i & 1);
                if (row >= M) continue;
                float v = acc[mt][nt][i];
                if (bias) v += bias[col];
                if (add)  v += add[(size_t)row * ldc + col];
                if (act)  v = fmaxf(v, 0.f);
                C[(size_t)row * ldc + col] = v;
            }
        }
    }
}

// ---------------- pack [gru_whh ; attn_w[:,512:]] into g_Wpack [2048,512] ------
__global__ void pack_kernel(const float* __restrict__ whh,
                            const float* __restrict__ attn_w)
{
    int i = blockIdx.x * 256 + threadIdx.x;      // 0 .. 2048*512-1
    int row = i >> 9, k = i & 511;
    float v;
    if (row < 1536) v = whh[i];
    else            v = attn_w[(row - 1536) * 1024 + 512 + k];
    g_Wpack[i] = v;
}

// ---------------- direct conv: features[B,2048,8,8] * conv_w[32,2048,3,3], pad1
__global__ __launch_bounds__(256) void conv_kernel(
    const float* __restrict__ features,
    const float* __restrict__ conv_w,
    const float* __restrict__ conv_b)
{
    __shared__ float sF[4][4][100];
    __shared__ float sW[4][4][32][9];
    __shared__ float sRed[2][64][32];

    const int b = blockIdx.x;
    const int tid = threadIdx.x;
    const int qid = tid >> 6;
    const int t2  = tid & 63;
    const int coutg = t2 >> 4;
    const int sg    = t2 & 15;

    for (int e = tid; e < 4 * 4 * 100; e += 256)
        (&sF[0][0][0])[e] = 0.f;

    int fb[4];
#pragma unroll
    for (int sp = 0; sp < 4; sp++) {
        int s = sg * 4 + sp;
        fb[sp] = (s >> 3) * 10 + (s & 7);
    }

    float acc[8][4];
#pragma unroll
    for (int co = 0; co < 8; co++)
#pragma unroll
        for (int sp = 0; sp < 4; sp++) acc[co][sp] = 0.f;

    for (int cbase = 0; cbase < 512; cbase += 4) {
        __syncthreads();
        for (int e = tid; e < 1024; e += 256) {
            int q = e >> 8, c = (e >> 6) & 3, s = e & 63;
            int y = s >> 3, x = s & 7;
            int cin = q * 512 + cbase + c;
            sF[q][c][(y + 1) * 10 + (x + 1)] =
                features[((size_t)b * 2048 + cin) * 64 + s];
        }
        for (int e = tid; e < 4608; e += 256) {
            int q = e / 1152, r = e % 1152;
            int c = r / 288, r2 = r % 288;
            int cout = r2 / 9, k = r2 % 9;
            int cin = q * 512 + cbase + c;
            sW[q][c][cout][k] = conv_w[((size_t)cout * 2048 + cin) * 9 + k];
        }
        __syncthreads();

#pragma unroll
        for (int c = 0; c < 4; c++) {
            const float* fp = &sF[qid][c][0];
            const float* wp = &sW[qid][c][0][0];
#pragma unroll
            for (int ky = 0; ky < 3; ky++) {
#pragma unroll
                for (int kx = 0; kx < 3; kx++) {
                    float wv[8];
#pragma unroll
                    for (int co = 0; co < 8; co++)
                        wv[co] = wp[(coutg * 8 + co) * 9 + ky * 3 + kx];
#pragma unroll
                    for (int sp = 0; sp < 4; sp++) {
                        float fv = fp[fb[sp] + ky * 10 + kx];
#pragma unroll
                        for (int co = 0; co < 8; co++)
                            acc[co][sp] += fv * wv[co];
                    }
                }
            }
        }
    }

    __syncthreads();
    if (qid >= 2) {
#pragma unroll
        for (int co = 0; co < 8; co++)
#pragma unroll
            for (int sp = 0; sp < 4; sp++)
                sRed[qid - 2][t2][co * 4 + sp] = acc[co][sp];
    }
    __syncthreads();
    if (qid < 2) {
#pragma unroll
        for (int co = 0; co < 8; co++)
#pragma unroll
            for (int sp = 0; sp < 4; sp++)
                acc[co][sp] += sRed[qid][t2][co * 4 + sp];
    }
    __syncthreads();
    if (qid == 1) {
#pragma unroll
        for (int co = 0; co < 8; co++)
#pragma unroll
            for (int sp = 0; sp < 4; sp++)
                sRed[0][t2][co * 4 + sp] = acc[co][sp];
    }
    __syncthreads();
    if (qid == 0) {
#pragma unroll
        for (int co = 0; co < 8; co++) {
            int cout = coutg * 8 + co;
            float bval = conv_b[cout];
#pragma unroll
            for (int sp = 0; sp < 4; sp++) {
                int s = sg * 4 + sp;
                g_Xc[(size_t)b * 2048 + cout * 64 + s] =
                    acc[co][sp] + sRed[0][t2][co * 4 + sp] + bval;
            }
        }
    }
}

// ---------------- BatchNorm1d with batch stats ---------------------------------
__global__ void bn_kernel(const float* __restrict__ bn_g,
                          const float* __restrict__ bn_b)
{
    __shared__ float red[256];
    const int h = blockIdx.x;
    const int b = threadIdx.x;
    float v = g_F0[(size_t)b * HH + h];
    red[b] = v;
    __syncthreads();
    for (int s = 128; s > 0; s >>= 1) {
        if (b < s) red[b] += red[b + s];
        __syncthreads();
    }
    float mu = red[0] / 256.f;
    __syncthreads();
    float d = v - mu;
    red[b] = d * d;
    __syncthreads();
    for (int s = 128; s > 0; s >>= 1) {
        if (b < s) red[b] += red[b + s];
        __syncthreads();
    }
    float var = red[0] / 256.f;
    float scale = rsqrtf(var + 1e-5f);
    g_F[(size_t)b * HH + h] = d * scale * bn_g[h] + bn_b[h];
}

// ---------------- gather packed embeddings into padded [T,B,E] -----------------
__global__ void gather_kernel(const int* __restrict__ pack_idx)
{
    int tb = blockIdx.x;
    int t = tb >> 8, b = tb & 255;
    int e = threadIdx.x;
    int idx = pack_idx[b * TT + t];
    float v = (idx >= 0) ? g_Emb[(size_t)idx * EE + e] : 0.f;
    g_Xpad[(size_t)tb * EE + e] = v;
}

__global__ void init_hx_kernel(const float* __restrict__ states)
{
    int i = blockIdx.x * blockDim.x + threadIdx.x;
    g_hx[i] = states[i];
}

// ---------------- softmax over h + attention gating (reads GhL L-part + xA) ----
__global__ void softmax_applied_kernel(int t)
{
    __shared__ float red[512];
    const int b = blockIdx.x;
    const int h = threadIdx.x;
    float v = g_GhL[(size_t)b * 2048 + 1536 + h]
            + g_xA[((size_t)t * BB + b) * HH + h];
    red[h] = v;
    __syncthreads();
    for (int s = 256; s > 0; s >>= 1) {
        if (h < s) red[h] = fmaxf(red[h], red[h + s]);
        __syncthreads();
    }
    float mx = red[0];
    __syncthreads();
    float e = expf(v - mx);
    red[h] = e;
    __syncthreads();
    for (int s = 256; s > 0; s >>= 1) {
        if (h < s) red[h] += red[h + s];
        __syncthreads();
    }
    float aw = e / red[0];
    g_applied[(size_t)b * HH + h] = g_F[(size_t)b * HH + h] * aw;
}

// ---------------- GRU gate combine + hidden update + capture at t==len-1 -------
__global__ void gru_gate_kernel(const int* __restrict__ lengths,
                                const float* __restrict__ gru_bhh,
                                float* __restrict__ hiddens, int t)
{
    const int b = blockIdx.x;
    const int h = threadIdx.x;
    size_t oG = (size_t)b * 2048;
    size_t oI = (size_t)b * 1536;
    float hr = g_GhL[oG + h]         + gru_bhh[h];
    float hz = g_GhL[oG + 512 + h]   + gru_bhh[512 + h];
    float hn = g_GhL[oG + 1024 + h]  + gru_bhh[1024 + h];
    float ir = g_Gi[oI + h];
    float iz = g_Gi[oI + 512 + h];
    float in_ = g_Gi[oI + 1024 + h];
    float r = 1.f / (1.f + expf(-(ir + hr)));
    float z = 1.f / (1.f + expf(-(iz + hz)));
    float n = tanhf(in_ + r * hn);
    float hprev = g_hx[(size_t)b * HH + h];
    float hnew = (1.f - z) * n + z * hprev;
    g_hx[(size_t)b * HH + h] = hnew;
    if (t == lengths[b] - 1)
        hiddens[(size_t)b * HH + h] = hnew;
}

// ---------------- build concat [hiddens, F] ------------------------------------
__global__ void cat_kernel(const float* __restrict__ hiddens)
{
    const int b = blockIdx.x;
    const int i = threadIdx.x;
    float v = (i < 512) ? hiddens[(size_t)b * HH + i]
                        : g_F[(size_t)b * HH + (i - 512)];
    g_Cat[(size_t)b * 1024 + i] = v;
}

// ---------------- final linear(1024->1) + sigmoid ------------------------------
__global__ void head_kernel(const float* __restrict__ lin3_w,
                            const float* __restrict__ lin3_b,
                            float* __restrict__ out)
{
    __shared__ float red[256];
    const int b = blockIdx.x;
    const int tid = threadIdx.x;
    float acc = 0.f;
#pragma unroll
    for (int k = 0; k < 4; k++) {
        int idx = tid + k * 256;
        acc += g_Y[(size_t)b * 1024 + idx] * lin3_w[idx];
    }
    red[tid] = acc;
    __syncthreads();
    for (int s = 128; s > 0; s >>= 1) {
        if (tid < s) red[tid] += red[tid + s];
        __syncthreads();
    }
    if (tid == 0) {
        float x = red[0] + lin3_b[0];
        out[b] = 1.f / (1.f + expf(-x));
    }
}

// ---------------- host orchestration ------------------------------------------
static void tgemm(const float* A, int lda, const float* W, int ldw,
                  const float* bias, const float* add,
                  float* C, int ldc, int M, int N, int K, int act)
{
    dim3 grid(N / 64, (M + 63) / 64);
    tgemm_kernel<<<grid, 128>>>(A, lda, W, ldw, bias, add, C, ldc, M, N, K, act);
}

extern "C" void kernel_launch(void* const* d_in, const int* in_sizes, int n_in,
                              void* d_out, int out_size)
{
    const float* features = (const float*)d_in[0];
    const float* captions = (const float*)d_in[1];
    const float* states   = (const float*)d_in[2];
    const int*   pack_idx = (const int*)d_in[3];
    const int*   lengths  = (const int*)d_in[4];
    const float* conv_w   = (const float*)d_in[5];
    const float* conv_b   = (const float*)d_in[6];
    const float* fc_w     = (const float*)d_in[7];
    const float* fc_b     = (const float*)d_in[8];
    const float* bn_g     = (const float*)d_in[9];
    const float* bn_b     = (const float*)d_in[10];
    const float* fc2_w    = (const float*)d_in[11];
    const float* fc2_b    = (const float*)d_in[12];
    const float* attn_w   = (const float*)d_in[13];
    const float* attn_b   = (const float*)d_in[14];
    const float* comb_w   = (const float*)d_in[15];
    const float* comb_b   = (const float*)d_in[16];
    const float* gru_wih  = (const float*)d_in[17];
    const float* gru_whh  = (const float*)d_in[18];
    const float* gru_bih  = (const float*)d_in[19];
    const float* gru_bhh  = (const float*)d_in[20];
    const float* lin_w    = (const float*)d_in[21];
    const float* lin_b    = (const float*)d_in[22];
    const float* lin3_w   = (const float*)d_in[23];
    const float* lin3_b   = (const float*)d_in[24];

    float* out = (float*)d_out;            // [0:256) sigmoid, [256: ) hiddens
    float* hiddens = out + 256;

    float *pXc, *pF0, *pEmb, *pXpad, *pxA, *pxC, *phx, *pGhL, *pGi;
    float *pApplied, *pInp, *pCat, *pY, *pWpack;
    cudaGetSymbolAddress((void**)&pXc, g_Xc);
    cudaGetSymbolAddress((void**)&pF0, g_F0);
    cudaGetSymbolAddress((void**)&pEmb, g_Emb);
    cudaGetSymbolAddress((void**)&pXpad, g_Xpad);
    cudaGetSymbolAddress((void**)&pxA, g_xA);
    cudaGetSymbolAddress((void**)&pxC, g_xC);
    cudaGetSymbolAddress((void**)&phx, g_hx);
    cudaGetSymbolAddress((void**)&pGhL, g_GhL);
    cudaGetSymbolAddress((void**)&pGi, g_Gi);
    cudaGetSymbolAddress((void**)&pApplied, g_applied);
    cudaGetSymbolAddress((void**)&pInp, g_inp);
    cudaGetSymbolAddress((void**)&pCat, g_Cat);
    cudaGetSymbolAddress((void**)&pY, g_Y);
    cudaGetSymbolAddress((void**)&pWpack, g_Wpack);

    // 0) pack hx-side weights [whh ; attn_wh] -> [2048, 512]
    pack_kernel<<<(2048 * 512) / 256, 256>>>(gru_whh, attn_w);
    // 1) conv -> g_Xc
    conv_kernel<<<256, 256>>>(features, conv_w, conv_b);
    // 2) fc: F0 = Xc @ fc_w^T + fc_b
    tgemm(pXc, 2048, fc_w, 2048, fc_b, nullptr, pF0, HH, BB, HH, 2048, 0);
    // 3) BN -> g_F
    bn_kernel<<<HH, 256>>>(bn_g, bn_b);
    // 4) emb = captions @ fc2_w^T + fc2_b
    tgemm(captions, VV, fc2_w, VV, fc2_b, nullptr, pEmb, EE, TTOT, EE, VV, 0);
    // 5) gather to padded [T,B,E]
    gather_kernel<<<TT * BB, EE>>>(pack_idx);
    // 6) x-part precompute GEMMs
    tgemm(pXpad, EE, attn_w, 1024, attn_b, nullptr, pxA, HH, TT * BB, HH, EE, 0);
    tgemm(pXpad, EE, comb_w, 1024, comb_b, nullptr, pxC, HH, TT * BB, HH, EE, 0);
    // 7) init hidden state
    init_hx_kernel<<<BB, HH>>>(states);

    // 8) sequential scan: 5 launches per step
    for (int t = 0; t < TT; t++) {
        // [Gh | Lh] = hx @ Wpack^T   (biases applied downstream)
        tgemm(phx, HH, pWpack, HH, nullptr, nullptr, pGhL, 2048, BB, 2048, HH, 0);
        softmax_applied_kernel<<<BB, HH>>>(t);
        // inp = relu(xC[t] + applied @ comb_wh^T)
        tgemm(pApplied, HH, comb_w + 512, 1024, nullptr,
              pxC + (size_t)t * BB * HH, pInp, HH, BB, HH, HH, 1);
        // gi = inp @ gru_wih^T + gru_bih
        tgemm(pInp, HH, gru_wih, HH, gru_bih, nullptr, pGi, 1536, BB, 1536, HH, 0);
        gru_gate_kernel<<<BB, HH>>>(lengths, gru_bhh, hiddens, t);
    }

    // 9) head
    cat_kernel<<<BB, 1024>>>(hiddens);
    tgemm(pCat, 1024, lin_w, 1024, lin_b, nullptr, pY, 1024, BB, 1024, 1024, 1);
    head_kernel<<<BB, 256>>>(lin3_w, lin3_b, out);
}

// round 3
// speedup vs baseline: 2.3899x; 1.2701x over previous
#include <cuda_runtime.h>
#include <cuda_bf16.h>
#include <math.h>

#define BB 256
#define HH 512
#define EE 512
#define VV 10000
#define TT 48
#define TTOT 9436

// ---------------- scratch (device globals; no allocation allowed) -------------
__device__ float g_Xc[BB * 2048];          // conv output flattened [B,2048]
__device__ float g_F0[BB * HH];            // pre-BN fc output
__device__ float g_F[BB * HH];             // BN'd features
__device__ float g_Emb[TTOT * EE];         // packed caption embeddings
__device__ float g_Xpad[TT * BB * EE];     // padded [T,B,E]
__device__ float g_xA[TT * BB * HH];       // x_t @ attn_w_x^T + attn_b
__device__ float g_xC[TT * BB * HH];       // x_t @ comb_w_x^T + comb_b
__device__ float g_hx[BB * HH];
__device__ float g_GhL[BB * 2048];         // [Gh(1536) | attn logits h-part(512)]
__device__ float g_Gi[BB * 3 * HH];
__device__ float g_applied[BB * HH];
__device__ float g_inp[BB * HH];
__device__ float g_Cat[BB * 2 * HH];
__device__ float g_Y[BB * 2 * HH];
__device__ float g_Wpack[2048 * 512];      // rows 0..1535: gru_whh; 1536..2047: attn_w[:,512:]

// ---------------- bf16 helpers -------------------------------------------------
__device__ __forceinline__ void mma_bf16(float c[4],
    unsigned a0, unsigned a1, unsigned a2, unsigned a3,
    unsigned b0, unsigned b1)
{
    asm volatile(
        "mma.sync.aligned.m16n8k16.row.col.f32.bf16.bf16.f32 "
        "{%0,%1,%2,%3}, {%4,%5,%6,%7}, {%8,%9}, {%0,%1,%2,%3};"
        : "+f"(c[0]), "+f"(c[1]), "+f"(c[2]), "+f"(c[3])
        : "r"(a0), "r"(a1), "r"(a2), "r"(a3), "r"(b0), "r"(b1));
}

// split float4 into packed bf16x2 hi/lo pairs (2 uints each)
__device__ __forceinline__ void split4(const float4 v,
    unsigned& h0, unsigned& h1, unsigned& l0, unsigned& l1)
{
    float f[4] = {v.x, v.y, v.z, v.w};
    __nv_bfloat16 hb[4], lb[4];
#pragma unroll
    for (int i = 0; i < 4; i++) {
        hb[i] = __float2bfloat16_rn(f[i]);
        lb[i] = __float2bfloat16_rn(f[i] - __bfloat162float(hb[i]));
    }
    __nv_bfloat162 t;
    t = __halves2bfloat162(hb[0], hb[1]); h0 = *reinterpret_cast<unsigned*>(&t);
    t = __halves2bfloat162(hb[2], hb[3]); h1 = *reinterpret_cast<unsigned*>(&t);
    t = __halves2bfloat162(lb[0], lb[1]); l0 = *reinterpret_cast<unsigned*>(&t);
    t = __halves2bfloat162(lb[2], lb[3]); l1 = *reinterpret_cast<unsigned*>(&t);
}

// ---------------- BF16x3 GEMM: C[M,N] = A[M,K] @ W[N,K]^T (+bias)(+add)(relu)
// BM=BN=64, BK=16, 128 threads (4 warps, 2x2), warp tile 32x32.
// Requires: N % 64 == 0, K % 16 == 0, lda/ldw % 4 == 0. M guarded.
// smem: packed bf16x2 along k, row stride 12 uints (conflict-free compute reads)
__global__ __launch_bounds__(128) void tgemm_kernel(
    const float* __restrict__ A, int lda,
    const float* __restrict__ W, int ldw,
    const float* __restrict__ bias,
    const float* __restrict__ add,
    float* __restrict__ C, int ldc,
    int M, int N, int K, int act)
{
    __shared__ unsigned Ah[64 * 12], Al[64 * 12];
    __shared__ unsigned Wh[64 * 12], Wl[64 * 12];

    const int tid  = threadIdx.x;
    const int lane = tid & 31;
    const int warp = tid >> 5;
    const int wm = (warp & 1) * 32;
    const int wn = (warp >> 1) * 32;
    const int m0 = blockIdx.y * 64;
    const int n0 = blockIdx.x * 64;

    const int lr = tid >> 2;          // 0..31 -> rows lr, lr+32
    const int lc = (tid & 3) * 4;     // k offset 0,4,8,12 (floats)
    const int lcu = lc >> 1;          // uint col 0,2,4,6

    float acc[2][4][4];
#pragma unroll
    for (int mt = 0; mt < 2; mt++)
#pragma unroll
        for (int nt = 0; nt < 4; nt++)
#pragma unroll
            for (int i = 0; i < 4; i++) acc[mt][nt][i] = 0.f;

    const int ar0 = m0 + lr, ar1 = m0 + lr + 32;
    const int wr0 = n0 + lr, wr1 = n0 + lr + 32;

    float4 av0, av1, wv0, wv1;
    const float4 z4 = make_float4(0.f, 0.f, 0.f, 0.f);

    av0 = (ar0 < M) ? *(const float4*)(A + (size_t)ar0 * lda + lc) : z4;
    av1 = (ar1 < M) ? *(const float4*)(A + (size_t)ar1 * lda + lc) : z4;
    wv0 = *(const float4*)(W + (size_t)wr0 * ldw + lc);
    wv1 = *(const float4*)(W + (size_t)wr1 * ldw + lc);

    const int krow = lane >> 2;   // 0..7
    const int kcol = lane & 3;    // 0..3 (uint cols; pairs k=2c,2c+1)

    for (int kk = 0; kk < K; kk += 16) {
        // split + store prefetched tile
        {
            unsigned h0, h1, l0, l1;
            split4(av0, h0, h1, l0, l1);
            *(uint2*)&Ah[lr * 12 + lcu] = make_uint2(h0, h1);
            *(uint2*)&Al[lr * 12 + lcu] = make_uint2(l0, l1);
            split4(av1, h0, h1, l0, l1);
            *(uint2*)&Ah[(lr + 32) * 12 + lcu] = make_uint2(h0, h1);
            *(uint2*)&Al[(lr + 32) * 12 + lcu] = make_uint2(l0, l1);
            split4(wv0, h0, h1, l0, l1);
            *(uint2*)&Wh[lr * 12 + lcu] = make_uint2(h0, h1);
            *(uint2*)&Wl[lr * 12 + lcu] = make_uint2(l0, l1);
            split4(wv1, h0, h1, l0, l1);
            *(uint2*)&Wh[(lr + 32) * 12 + lcu] = make_uint2(h0, h1);
            *(uint2*)&Wl[(lr + 32) * 12 + lcu] = make_uint2(l0, l1);
        }
        __syncthreads();

        // prefetch next tile
        if (kk + 16 < K) {
            int k2 = kk + 16 + lc;
            av0 = (ar0 < M) ? *(const float4*)(A + (size_t)ar0 * lda + k2) : z4;
            av1 = (ar1 < M) ? *(const float4*)(A + (size_t)ar1 * lda + k2) : z4;
            wv0 = *(const float4*)(W + (size_t)wr0 * ldw + k2);
            wv1 = *(const float4*)(W + (size_t)wr1 * ldw + k2);
        }

        // compute: one k16 step, 24 MMAs per warp
        unsigned ah[2][4], al_[2][4], bh[4][2], bl[4][2];
#pragma unroll
        for (int mt = 0; mt < 2; mt++) {
            int r = wm + mt * 16 + krow;
            int o0 = r * 12 + kcol;
            int o1 = (r + 8) * 12 + kcol;
            ah[mt][0] = Ah[o0];     ah[mt][1] = Ah[o1];
            ah[mt][2] = Ah[o0 + 4]; ah[mt][3] = Ah[o1 + 4];
            al_[mt][0] = Al[o0];     al_[mt][1] = Al[o1];
            al_[mt][2] = Al[o0 + 4]; al_[mt][3] = Al[o1 + 4];
        }
#pragma unroll
        for (int nt = 0; nt < 4; nt++) {
            int cn = wn + nt * 8 + krow;
            int o = cn * 12 + kcol;
            bh[nt][0] = Wh[o]; bh[nt][1] = Wh[o + 4];
            bl[nt][0] = Wl[o]; bl[nt][1] = Wl[o + 4];
        }
#pragma unroll
        for (int mt = 0; mt < 2; mt++)
#pragma unroll
            for (int nt = 0; nt < 4; nt++) {
                mma_bf16(acc[mt][nt], ah[mt][0], ah[mt][1], ah[mt][2], ah[mt][3],
                         bh[nt][0], bh[nt][1]);
                mma_bf16(acc[mt][nt], ah[mt][0], ah[mt][1], ah[mt][2], ah[mt][3],
                         bl[nt][0], bl[nt][1]);
                mma_bf16(acc[mt][nt], al_[mt][0], al_[mt][1], al_[mt][2], al_[mt][3],
                         bh[nt][0], bh[nt][1]);
            }
        __syncthreads();
    }

    // epilogue
#pragma unroll
    for (int mt = 0; mt < 2; mt++) {
#pragma unroll
        for (int nt = 0; nt < 4; nt++) {
            int r0 = m0 + wm + mt * 16 + (lane >> 2);
            int c0 = n0 + wn + nt * 8 + (lane & 3) * 2;
#pragma unroll
            for (int i = 0; i < 4; i++) {
                int row = r0 + (i >> 1) * 8;
                int col = c0 + (i & 1);
                if (row >= M) continue;
                float v = acc[mt][nt][i];
                if (bias) v += bias[col];
                if (add)  v += add[(size_t)row * ldc + col];
                if (act)  v = fmaxf(v, 0.f);
                C[(size_t)row * ldc + col] = v;
            }
        }
    }
}

// ---------------- pack [gru_whh ; attn_w[:,512:]] into g_Wpack [2048,512] ------
__global__ void pack_kernel(const float* __restrict__ whh,
                            const float* __restrict__ attn_w)
{
    int i = blockIdx.x * 256 + threadIdx.x;      // 0 .. 2048*512-1
    int row = i >> 9, k = i & 511;
    float v;
    if (row < 1536) v = whh[i];
    else            v = attn_w[(row - 1536) * 1024 + 512 + k];
    g_Wpack[i] = v;
}

// ---------------- direct conv: features[B,2048,8,8] * conv_w[32,2048,3,3], pad1
__global__ __launch_bounds__(256) void conv_kernel(
    const float* __restrict__ features,
    const float* __restrict__ conv_w,
    const float* __restrict__ conv_b)
{
    __shared__ float sF[4][4][100];
    __shared__ float sW[4][4][32][9];
    __shared__ float sRed[2][64][32];

    const int b = blockIdx.x;
    const int tid = threadIdx.x;
    const int qid = tid >> 6;
    const int t2  = tid & 63;
    const int coutg = t2 >> 4;
    const int sg    = t2 & 15;

    for (int e = tid; e < 4 * 4 * 100; e += 256)
        (&sF[0][0][0])[e] = 0.f;

    int fb[4];
#pragma unroll
    for (int sp = 0; sp < 4; sp++) {
        int s = sg * 4 + sp;
        fb[sp] = (s >> 3) * 10 + (s & 7);
    }

    float acc[8][4];
#pragma unroll
    for (int co = 0; co < 8; co++)
#pragma unroll
        for (int sp = 0; sp < 4; sp++) acc[co][sp] = 0.f;

    for (int cbase = 0; cbase < 512; cbase += 4) {
        __syncthreads();
        for (int e = tid; e < 1024; e += 256) {
            int q = e >> 8, c = (e >> 6) & 3, s = e & 63;
            int y = s >> 3, x = s & 7;
            int cin = q * 512 + cbase + c;
            sF[q][c][(y + 1) * 10 + (x + 1)] =
                features[((size_t)b * 2048 + cin) * 64 + s];
        }
        for (int e = tid; e < 4608; e += 256) {
            int q = e / 1152, r = e % 1152;
            int c = r / 288, r2 = r % 288;
            int cout = r2 / 9, k = r2 % 9;
            int cin = q * 512 + cbase + c;
            sW[q][c][cout][k] = conv_w[((size_t)cout * 2048 + cin) * 9 + k];
        }
        __syncthreads();

#pragma unroll
        for (int c = 0; c < 4; c++) {
            const float* fp = &sF[qid][c][0];
            const float* wp = &sW[qid][c][0][0];
#pragma unroll
            for (int ky = 0; ky < 3; ky++) {
#pragma unroll
                for (int kx = 0; kx < 3; kx++) {
                    float wv[8];
#pragma unroll
                    for (int co = 0; co < 8; co++)
                        wv[co] = wp[(coutg * 8 + co) * 9 + ky * 3 + kx];
#pragma unroll
                    for (int sp = 0; sp < 4; sp++) {
                        float fv = fp[fb[sp] + ky * 10 + kx];
#pragma unroll
                        for (int co = 0; co < 8; co++)
                            acc[co][sp] += fv * wv[co];
                    }
                }
            }
        }
    }

    __syncthreads();
    if (qid >= 2) {
#pragma unroll
        for (int co = 0; co < 8; co++)
#pragma unroll
            for (int sp = 0; sp < 4; sp++)
                sRed[qid - 2][t2][co * 4 + sp] = acc[co][sp];
    }
    __syncthreads();
    if (qid < 2) {
#pragma unroll
        for (int co = 0; co < 8; co++)
#pragma unroll
            for (int sp = 0; sp < 4; sp++)
                acc[co][sp] += sRed[qid][t2][co * 4 + sp];
    }
    __syncthreads();
    if (qid == 1) {
#pragma unroll
        for (int co = 0; co < 8; co++)
#pragma unroll
            for (int sp = 0; sp < 4; sp++)
                sRed[0][t2][co * 4 + sp] = acc[co][sp];
    }
    __syncthreads();
    if (qid == 0) {
#pragma unroll
        for (int co = 0; co < 8; co++) {
            int cout = coutg * 8 + co;
            float bval = conv_b[cout];
#pragma unroll
            for (int sp = 0; sp < 4; sp++) {
                int s = sg * 4 + sp;
                g_Xc[(size_t)b * 2048 + cout * 64 + s] =
                    acc[co][sp] + sRed[0][t2][co * 4 + sp] + bval;
            }
        }
    }
}

// ---------------- BatchNorm1d with batch stats ---------------------------------
__global__ void bn_kernel(const float* __restrict__ bn_g,
                          const float* __restrict__ bn_b)
{
    __shared__ float red[256];
    const int h = blockIdx.x;
    const int b = threadIdx.x;
    float v = g_F0[(size_t)b * HH + h];
    red[b] = v;
    __syncthreads();
    for (int s = 128; s > 0; s >>= 1) {
        if (b < s) red[b] += red[b + s];
        __syncthreads();
    }
    float mu = red[0] / 256.f;
    __syncthreads();
    float d = v - mu;
    red[b] = d * d;
    __syncthreads();
    for (int s = 128; s > 0; s >>= 1) {
        if (b < s) red[b] += red[b + s];
        __syncthreads();
    }
    float var = red[0] / 256.f;
    float scale = rsqrtf(var + 1e-5f);
    g_F[(size_t)b * HH + h] = d * scale * bn_g[h] + bn_b[h];
}

// ---------------- gather packed embeddings into padded [T,B,E] -----------------
__global__ void gather_kernel(const int* __restrict__ pack_idx)
{
    int tb = blockIdx.x;
    int t = tb >> 8, b = tb & 255;
    int e = threadIdx.x;
    int idx = pack_idx[b * TT + t];
    float v = (idx >= 0) ? g_Emb[(size_t)idx * EE + e] : 0.f;
    g_Xpad[(size_t)tb * EE + e] = v;
}

__global__ void init_hx_kernel(const float* __restrict__ states)
{
    int i = blockIdx.x * blockDim.x + threadIdx.x;
    g_hx[i] = states[i];
}

// ---------------- softmax over h + attention gating (reads GhL L-part + xA) ----
__global__ void softmax_applied_kernel(int t)
{
    __shared__ float red[512];
    const int b = blockIdx.x;
    const int h = threadIdx.x;
    float v = g_GhL[(size_t)b * 2048 + 1536 + h]
            + g_xA[((size_t)t * BB + b) * HH + h];
    red[h] = v;
    __syncthreads();
    for (int s = 256; s > 0; s >>= 1) {
        if (h < s) red[h] = fmaxf(red[h], red[h + s]);
        __syncthreads();
    }
    float mx = red[0];
    __syncthreads();
    float e = expf(v - mx);
    red[h] = e;
    __syncthreads();
    for (int s = 256; s > 0; s >>= 1) {
        if (h < s) red[h] += red[h + s];
        __syncthreads();
    }
    float aw = e / red[0];
    g_applied[(size_t)b * HH + h] = g_F[(size_t)b * HH + h] * aw;
}

// ---------------- GRU gate combine + hidden update + capture at t==len-1 -------
__global__ void gru_gate_kernel(const int* __restrict__ lengths,
                                const float* __restrict__ gru_bhh,
                                float* __restrict__ hiddens, int t)
{
    const int b = blockIdx.x;
    const int h = threadIdx.x;
    size_t oG = (size_t)b * 2048;
    size_t oI = (size_t)b * 1536;
    float hr = g_GhL[oG + h]         + gru_bhh[h];
    float hz = g_GhL[oG + 512 + h]   + gru_bhh[512 + h];
    float hn = g_GhL[oG + 1024 + h]  + gru_bhh[1024 + h];
    float ir = g_Gi[oI + h];
    float iz = g_Gi[oI + 512 + h];
    float in_ = g_Gi[oI + 1024 + h];
    float r = 1.f / (1.f + expf(-(ir + hr)));
    float z = 1.f / (1.f + expf(-(iz + hz)));
    float n = tanhf(in_ + r * hn);
    float hprev = g_hx[(size_t)b * HH + h];
    float hnew = (1.f - z) * n + z * hprev;
    g_hx[(size_t)b * HH + h] = hnew;
    if (t == lengths[b] - 1)
        hiddens[(size_t)b * HH + h] = hnew;
}

// ---------------- build concat [hiddens, F] ------------------------------------
__global__ void cat_kernel(const float* __restrict__ hiddens)
{
    const int b = blockIdx.x;
    const int i = threadIdx.x;
    float v = (i < 512) ? hiddens[(size_t)b * HH + i]
                        : g_F[(size_t)b * HH + (i - 512)];
    g_Cat[(size_t)b * 1024 + i] = v;
}

// ---------------- final linear(1024->1) + sigmoid ------------------------------
__global__ void head_kernel(const float* __restrict__ lin3_w,
                            const float* __restrict__ lin3_b,
                            float* __restrict__ out)
{
    __shared__ float red[256];
    const int b = blockIdx.x;
    const int tid = threadIdx.x;
    float acc = 0.f;
#pragma unroll
    for (int k = 0; k < 4; k++) {
        int idx = tid + k * 256;
        acc += g_Y[(size_t)b * 1024 + idx] * lin3_w[idx];
    }
    red[tid] = acc;
    __syncthreads();
    for (int s = 128; s > 0; s >>= 1) {
        if (tid < s) red[tid] += red[tid + s];
        __syncthreads();
    }
    if (tid == 0) {
        float x = red[0] + lin3_b[0];
        out[b] = 1.f / (1.f + expf(-x));
    }
}

// ---------------- host orchestration ------------------------------------------
static void tgemm(const float* A, int lda, const float* W, int ldw,
                  const float* bias, const float* add,
                  float* C, int ldc, int M, int N, int K, int act)
{
    dim3 grid(N / 64, (M + 63) / 64);
    tgemm_kernel<<<grid, 128>>>(A, lda, W, ldw, bias, add, C, ldc, M, N, K, act);
}

extern "C" void kernel_launch(void* const* d_in, const int* in_sizes, int n_in,
                              void* d_out, int out_size)
{
    const float* features = (const float*)d_in[0];
    const float* captions = (const float*)d_in[1];
    const float* states   = (const float*)d_in[2];
    const int*   pack_idx = (const int*)d_in[3];
    const int*   lengths  = (const int*)d_in[4];
    const float* conv_w   = (const float*)d_in[5];
    const float* conv_b   = (const float*)d_in[6];
    const float* fc_w     = (const float*)d_in[7];
    const float* fc_b     = (const float*)d_in[8];
    const float* bn_g     = (const float*)d_in[9];
    const float* bn_b     = (const float*)d_in[10];
    const float* fc2_w    = (const float*)d_in[11];
    const float* fc2_b    = (const float*)d_in[12];
    const float* attn_w   = (const float*)d_in[13];
    const float* attn_b   = (const float*)d_in[14];
    const float* comb_w   = (const float*)d_in[15];
    const float* comb_b   = (const float*)d_in[16];
    const float* gru_wih  = (const float*)d_in[17];
    const float* gru_whh  = (const float*)d_in[18];
    const float* gru_bih  = (const float*)d_in[19];
    const float* gru_bhh  = (const float*)d_in[20];
    const float* lin_w    = (const float*)d_in[21];
    const float* lin_b    = (const float*)d_in[22];
    const float* lin3_w   = (const float*)d_in[23];
    const float* lin3_b   = (const float*)d_in[24];

    float* out = (float*)d_out;            // [0:256) sigmoid, [256: ) hiddens
    float* hiddens = out + 256;

    float *pXc, *pF0, *pEmb, *pXpad, *pxA, *pxC, *phx, *pGhL, *pGi;
    float *pApplied, *pInp, *pCat, *pY, *pWpack;
    cudaGetSymbolAddress((void**)&pXc, g_Xc);
    cudaGetSymbolAddress((void**)&pF0, g_F0);
    cudaGetSymbolAddress((void**)&pEmb, g_Emb);
    cudaGetSymbolAddress((void**)&pXpad, g_Xpad);
    cudaGetSymbolAddress((void**)&pxA, g_xA);
    cudaGetSymbolAddress((void**)&pxC, g_xC);
    cudaGetSymbolAddress((void**)&phx, g_hx);
    cudaGetSymbolAddress((void**)&pGhL, g_GhL);
    cudaGetSymbolAddress((void**)&pGi, g_Gi);
    cudaGetSymbolAddress((void**)&pApplied, g_applied);
    cudaGetSymbolAddress((void**)&pInp, g_inp);
    cudaGetSymbolAddress((void**)&pCat, g_Cat);
    cudaGetSymbolAddress((void**)&pY, g_Y);
    cudaGetSymbolAddress((void**)&pWpack, g_Wpack);

    // 0) pack hx-side weights [whh ; attn_wh] -> [2048, 512]
    pack_kernel<<<(2048 * 512) / 256, 256>>>(gru_whh, attn_w);
    // 1) conv -> g_Xc
    conv_kernel<<<256, 256>>>(features, conv_w, conv_b);
    // 2) fc: F0 = Xc @ fc_w^T + fc_b
    tgemm(pXc, 2048, fc_w, 2048, fc_b, nullptr, pF0, HH, BB, HH, 2048, 0);
    // 3) BN -> g_F
    bn_kernel<<<HH, 256>>>(bn_g, bn_b);
    // 4) emb = captions @ fc2_w^T + fc2_b
    tgemm(captions, VV, fc2_w, VV, fc2_b, nullptr, pEmb, EE, TTOT, EE, VV, 0);
    // 5) gather to padded [T,B,E]
    gather_kernel<<<TT * BB, EE>>>(pack_idx);
    // 6) x-part precompute GEMMs
    tgemm(pXpad, EE, attn_w, 1024, attn_b, nullptr, pxA, HH, TT * BB, HH, EE, 0);
    tgemm(pXpad, EE, comb_w, 1024, comb_b, nullptr, pxC, HH, TT * BB, HH, EE, 0);
    // 7) init hidden state
    init_hx_kernel<<<BB, HH>>>(states);

    // 8) sequential scan: 5 launches per step
    for (int t = 0; t < TT; t++) {
        // [Gh | Lh] = hx @ Wpack^T   (biases applied downstream)
        tgemm(phx, HH, pWpack, HH, nullptr, nullptr, pGhL, 2048, BB, 2048, HH, 0);
        softmax_applied_kernel<<<BB, HH>>>(t);
        // inp = relu(xC[t] + applied @ comb_wh^T)
        tgemm(pApplied, HH, comb_w + 512, 1024, nullptr,
              pxC + (size_t)t * BB * HH, pInp, HH, BB, HH, HH, 1);
        // gi = inp @ gru_wih^T + gru_bih
        tgemm(pInp, HH, gru_wih, HH, gru_bih, nullptr, pGi, 1536, BB, 1536, HH, 0);
        gru_gate_kernel<<<BB, HH>>>(lengths, gru_bhh, hiddens, t);
    }

    // 9) head
    cat_kernel<<<BB, 1024>>>(hiddens);
    tgemm(pCat, 1024, lin_w, 1024, lin_b, nullptr, pY, 1024, BB, 1024, 1024, 1);
    head_kernel<<<BB, 256>>>(lin3_w, lin3_b, out);
}